// round 9
// baseline (speedup 1.0000x reference)
#include <cuda_runtime.h>

#define BB 2
#define NN 65536
#define KK 16
#define DD 32
#define NPTS (BB*NN)                 // 131072 points

// ---- k_block config: 128 threads, 4 warps, 32 pts/warp (4 groups x 8 sets)
#define KB_THREADS 128
#define KB_WARPS 4
#define SETS 8
#define PTS_PER_WARP 32
#define KB_GRID (NPTS/(KB_WARPS*PTS_PER_WARP))       // 1024

// ---- k_transform config: 256 threads, 8 pts/warp (tiny kernel)
#define KT_THREADS 256
#define KT_SETS 2
#define KT_GRID (NPTS/(8*8))                          // 2048

// Scratch (no cudaMalloc allowed): ping-pong z buffers + residual state.
__device__ float g_za[NPTS*DD];
__device__ float g_zb[NPTS*DD];
__device__ float g_prev[NPTS*DD];
__device__ float g_acc [NPTS*DD];

__device__ __forceinline__ float lrelu1(float v) { return v >= 0.f ? v : 0.2f*v; }
__device__ __forceinline__ float4 lrelu4(float4 v) {
    return make_float4(lrelu1(v.x), lrelu1(v.y), lrelu1(v.z), lrelu1(v.w));
}
__device__ __forceinline__ float4 max4(float4 a, float4 b) {
    return make_float4(fmaxf(a.x,b.x), fmaxf(a.y,b.y), fmaxf(a.z,b.z), fmaxf(a.w,b.w));
}
__device__ __forceinline__ void add4(float4& a, float4 b) {
    a.x += b.x; a.y += b.y; a.z += b.z; a.w += b.w;
}
__device__ __forceinline__ void fma4(float4& o, float s, float4 w) {
    o.x = fmaf(s, w.x, o.x); o.y = fmaf(s, w.y, o.y);
    o.z = fmaf(s, w.z, o.z); o.w = fmaf(s, w.w, o.w);
}
__device__ __forceinline__ float4 affine4(float4 a, float4 g, float4 b) {
    return make_float4(fmaf(a.x,g.x,b.x), fmaf(a.y,g.y,b.y),
                       fmaf(a.z,g.z,b.z), fmaf(a.w,g.w,b.w));
}
__device__ __forceinline__ float4 relu4(float4 v) {
    return make_float4(fmaxf(v.x,0.f), fmaxf(v.y,0.f), fmaxf(v.z,0.f), fmaxf(v.w,0.f));
}
__device__ __forceinline__ float sel4(const float4& v, int c) {
    return (c&3)==0 ? v.x : (c&3)==1 ? v.y : (c&3)==2 ? v.z : v.w;
}
__device__ __forceinline__ int sel4i(const int4& v, int c) {
    return (c&3)==0 ? v.x : (c&3)==1 ? v.y : (c&3)==2 ? v.z : v.w;
}
// Broadcast channel c (0..31) of this group's point: owner lane grp*8 + c/4.
// One SHFL serves all 4 groups at once.
__device__ __forceinline__ float bc(const float4& v, int c, int grp) {
    return __shfl_sync(0xffffffffu, sel4(v, c), (grp<<3) + (c>>2));
}

// K0: z0 = relu((x @ W2) * g2 + b2). 8 pts/warp: 4 groups x 2 sets, 8 lanes/pt.
__global__ void __launch_bounds__(KT_THREADS, 3)
k_transform(const float* __restrict__ x,
            const float* __restrict__ W2,
            const float* __restrict__ g2,
            const float* __restrict__ b2)
{
    __shared__ float4 sW2[DD*8];
    int tid = threadIdx.x;
    for (int i = tid; i < DD*8; i += KT_THREADS)
        sW2[i] = reinterpret_cast<const float4*>(W2)[i];
    __syncthreads();

    int lane = tid & 31, wid = tid >> 5;
    int grp = lane >> 3, sub = lane & 7;
    unsigned base = (blockIdx.x * 8 + wid) * 8;
    const float4* xf = reinterpret_cast<const float4*>(x);

    unsigned off[KT_SETS];
    float4 xv[KT_SETS], a[KT_SETS];
    #pragma unroll
    for (int s = 0; s < KT_SETS; s++) {
        off[s] = (base + s*4 + grp)*8 + sub;
        xv[s]  = __ldg(xf + off[s]);
        a[s]   = make_float4(0.f,0.f,0.f,0.f);
    }
    #pragma unroll
    for (int c = 0; c < DD; c++) {
        float4 w = sW2[c*8 + sub];
        #pragma unroll
        for (int s = 0; s < KT_SETS; s++)
            fma4(a[s], bc(xv[s], c, grp), w);
    }
    float4 gv = __ldg(reinterpret_cast<const float4*>(g2) + sub);
    float4 bv = __ldg(reinterpret_cast<const float4*>(b2) + sub);
    float4* za = reinterpret_cast<float4*>(g_za);
    #pragma unroll
    for (int s = 0; s < KT_SETS; s++)
        za[off[s]] = relu4(affine4(a[s], gv, bv));
}

// One network block fused with the NEXT block's per-point transform.
// MODE 0: first (init acc/prev). MODE 1: middle. MODE 2: last (write out).
template<int MODE>
__global__ void __launch_bounds__(KB_THREADS, 3)
k_block(int zflag,
        const int*   __restrict__ idx,
        const float* __restrict__ W1,  const float* __restrict__ g1,  const float* __restrict__ b1,
        const float* __restrict__ W2n, const float* __restrict__ g2n, const float* __restrict__ b2n,
        float* __restrict__ out)
{
    __shared__ float4 sW1[2*DD*8];            // 8 KB
    __shared__ float4 sW2[DD*8];              // 4 KB
    int tid = threadIdx.x;
    for (int i = tid; i < 2*DD*8; i += KB_THREADS)
        sW1[i] = reinterpret_cast<const float4*>(W1)[i];
    if (MODE != 2)
        for (int i = tid; i < DD*8; i += KB_THREADS)
            sW2[i] = reinterpret_cast<const float4*>(W2n)[i];
    __syncthreads();

    int lane = tid & 31, wid = tid >> 5;
    int grp = lane >> 3, sub = lane & 7;
    unsigned base = (blockIdx.x * KB_WARPS + wid) * PTS_PER_WARP;
    int b = base >> 16;                        // all 32 pts share the batch
    const float* z_in  = zflag ? g_zb : g_za;
    float*       z_out = zflag ? g_za : g_zb;
    const float4* zb = reinterpret_cast<const float4*>(z_in) + (unsigned)(b) * (NN*8u);

    // 512 neighbor indices for the warp's 32 points: four int4 per lane.
    // Point p = s*4+grp owns global int4 slots p*4+k/4; reg = s/2,
    // lane slot = (s&1)*16 + grp*4 + k/4.
    const int4* ip = reinterpret_cast<const int4*>(idx) + base*4u;
    int4 iv[4];
    #pragma unroll
    for (int r = 0; r < 4; r++)
        iv[r] = __ldg(ip + r*32 + lane);

    // Gather + max/mean over k. Per k per set: 1 SHFL + 1 LDG.128.
    // 128 independent LDG.128 per warp -> gather is throughput-bound, not
    // latency-bound.
    float4 mx[SETS], sm[SETS];
    #pragma unroll
    for (int s = 0; s < SETS; s++) {
        mx[s] = make_float4(-1e30f,-1e30f,-1e30f,-1e30f);
        sm[s] = make_float4(0.f,0.f,0.f,0.f);
    }
    #pragma unroll
    for (int k = 0; k < KK; k++) {
        #pragma unroll
        for (int s = 0; s < SETS; s++) {
            int slot = ((s & 1) << 4) + (grp << 2) + (k >> 2);
            int j = __shfl_sync(0xffffffffu, sel4i(iv[s >> 1], k), slot);
            float4 v = __ldg(zb + (unsigned)j*8u + sub);
            mx[s] = max4(mx[s], v);
            add4(sm[s], v);
        }
    }
    const float r16 = 1.f/KK;
    #pragma unroll
    for (int s = 0; s < SETS; s++) {
        sm[s].x *= r16; sm[s].y *= r16; sm[s].z *= r16; sm[s].w *= r16;
    }

    // Second 1x1 conv. Weight rows loaded from shared once per c, reused
    // across all 8 sets.
    float4 o[SETS];
    #pragma unroll
    for (int s = 0; s < SETS; s++) o[s] = make_float4(0.f,0.f,0.f,0.f);
    #pragma unroll
    for (int c = 0; c < DD; c++) {
        float4 wa = sW1[c*8 + sub];
        float4 wb = sW1[(DD + c)*8 + sub];
        #pragma unroll
        for (int s = 0; s < SETS; s++) {
            fma4(o[s], bc(mx[s], c, grp), wa);
            fma4(o[s], bc(sm[s], c, grp), wb);
        }
    }
    float4 g1v = __ldg(reinterpret_cast<const float4*>(g1) + sub);
    float4 b1v = __ldg(reinterpret_cast<const float4*>(b1) + sub);
    float4 xv[SETS];
    #pragma unroll
    for (int s = 0; s < SETS; s++)
        xv[s] = affine4(o[s], g1v, b1v);

    float4* accp  = reinterpret_cast<float4*>(g_acc);
    float4* prevp = reinterpret_cast<float4*>(g_prev);
    float4 sres[SETS];
    if (MODE == 0) {
        #pragma unroll
        for (int s = 0; s < SETS; s++) {
            unsigned off = (base + s*4 + grp)*8 + sub;
            accp[off]  = xv[s];
            prevp[off] = xv[s];
            sres[s] = xv[s];
        }
    } else if (MODE == 1) {
        #pragma unroll
        for (int s = 0; s < SETS; s++) {
            unsigned off = (base + s*4 + grp)*8 + sub;
            float4 p = prevp[off];
            sres[s] = make_float4(xv[s].x+p.x, xv[s].y+p.y, xv[s].z+p.z, xv[s].w+p.w);
            float4 ac = accp[off];
            add4(ac, xv[s]);
            accp[off]  = ac;
            prevp[off] = xv[s];
        }
    } else {
        float4* outp = reinterpret_cast<float4*>(out);
        #pragma unroll
        for (int s = 0; s < SETS; s++) {
            unsigned off = (base + s*4 + grp)*8 + sub;
            float4 ac = accp[off];
            add4(ac, xv[s]);
            outp[off] = lrelu4(ac);            // lrelu(x1+x2+x3+x4)
        }
        return;
    }

    // Fused next-block transform: z_next = relu((lrelu(s) @ W2n) * g2n + b2n)
    float4 t[SETS], a2[SETS];
    #pragma unroll
    for (int s = 0; s < SETS; s++) {
        t[s]  = lrelu4(sres[s]);
        a2[s] = make_float4(0.f,0.f,0.f,0.f);
    }
    #pragma unroll
    for (int c = 0; c < DD; c++) {
        float4 w = sW2[c*8 + sub];
        #pragma unroll
        for (int s = 0; s < SETS; s++)
            fma4(a2[s], bc(t[s], c, grp), w);
    }
    float4 g2v = __ldg(reinterpret_cast<const float4*>(g2n) + sub);
    float4 b2v = __ldg(reinterpret_cast<const float4*>(b2n) + sub);
    float4* zo = reinterpret_cast<float4*>(z_out);
    #pragma unroll
    for (int s = 0; s < SETS; s++) {
        unsigned off = (base + s*4 + grp)*8 + sub;
        zo[off] = relu4(affine4(a2[s], g2v, b2v));
    }
}

extern "C" void kernel_launch(void* const* d_in, const int* in_sizes, int n_in,
                              void* d_out, int out_size)
{
    const float* x   = (const float*)d_in[0];   // (2,65536,32)
    const int*   idx = (const int*)  d_in[1];   // (2,65536,16)
    const float* W2d = (const float*)d_in[2];   // (4,32,32)
    const float* g2  = (const float*)d_in[3];   // (4,32)
    const float* b2  = (const float*)d_in[4];   // (4,32)
    const float* W1d = (const float*)d_in[5];   // (4,64,32)
    const float* g1  = (const float*)d_in[6];   // (4,32)
    const float* b1  = (const float*)d_in[7];   // (4,32)
    float* out = (float*)d_out;

    // z0 from block-0 transform
    k_transform<<<KT_GRID, KT_THREADS>>>(x, W2d, g2, b2);

    dim3 blk(KB_THREADS), grd(KB_GRID);
    // block 0: reads g_za, writes x1 state + z1 into g_zb (tail = block-1 weights)
    k_block<0><<<grd, blk>>>(0, idx,
                             W1d + 0*2048, g1 + 0*32, b1 + 0*32,
                             W2d + 1*1024, g2 + 1*32, b2 + 1*32, out);
    // block 1: reads g_zb, writes z2 into g_za (tail = block-2 weights)
    k_block<1><<<grd, blk>>>(1, idx,
                             W1d + 1*2048, g1 + 1*32, b1 + 1*32,
                             W2d + 2*1024, g2 + 2*32, b2 + 2*32, out);
    // block 2: reads g_za, writes z3 into g_zb (tail = block-3 weights)
    k_block<1><<<grd, blk>>>(0, idx,
                             W1d + 2*2048, g1 + 2*32, b1 + 2*32,
                             W2d + 3*1024, g2 + 3*32, b2 + 3*32, out);
    // block 3: reads g_zb, writes final output
    k_block<2><<<grd, blk>>>(1, idx,
                             W1d + 3*2048, g1 + 3*32, b1 + 3*32,
                             W2d, g2, b2, out);
}

// round 10
// speedup vs baseline: 1.0058x; 1.0058x over previous
#include <cuda_runtime.h>

#define BB 2
#define NN 65536
#define KK 16
#define DD 32
#define NPTS (BB*NN)                 // 131072 points

// ---- k_block config: 128 threads, 4 warps, 32 pts/warp (4 groups x 8 sets)
#define KB_THREADS 128
#define KB_WARPS 4
#define SETS 8
#define PTS_PER_WARP 32
#define KB_GRID (NPTS/(KB_WARPS*PTS_PER_WARP))       // 1024

// ---- k_transform config: 256 threads, 8 pts/warp (tiny kernel)
#define KT_THREADS 256
#define KT_SETS 2
#define KT_GRID (NPTS/(8*8))                          // 2048

// Scratch (no cudaMalloc allowed): ping-pong z buffers + residual state.
__device__ float g_za[NPTS*DD];
__device__ float g_zb[NPTS*DD];
__device__ float g_prev[NPTS*DD];
__device__ float g_acc [NPTS*DD];

__device__ __forceinline__ float lrelu1(float v) { return v >= 0.f ? v : 0.2f*v; }
__device__ __forceinline__ float4 lrelu4(float4 v) {
    return make_float4(lrelu1(v.x), lrelu1(v.y), lrelu1(v.z), lrelu1(v.w));
}
__device__ __forceinline__ float4 max4(float4 a, float4 b) {
    return make_float4(fmaxf(a.x,b.x), fmaxf(a.y,b.y), fmaxf(a.z,b.z), fmaxf(a.w,b.w));
}
__device__ __forceinline__ void add4(float4& a, float4 b) {
    a.x += b.x; a.y += b.y; a.z += b.z; a.w += b.w;
}
__device__ __forceinline__ void fma4(float4& o, float s, float4 w) {
    o.x = fmaf(s, w.x, o.x); o.y = fmaf(s, w.y, o.y);
    o.z = fmaf(s, w.z, o.z); o.w = fmaf(s, w.w, o.w);
}
__device__ __forceinline__ float4 affine4(float4 a, float4 g, float4 b) {
    return make_float4(fmaf(a.x,g.x,b.x), fmaf(a.y,g.y,b.y),
                       fmaf(a.z,g.z,b.z), fmaf(a.w,g.w,b.w));
}
__device__ __forceinline__ float4 relu4(float4 v) {
    return make_float4(fmaxf(v.x,0.f), fmaxf(v.y,0.f), fmaxf(v.z,0.f), fmaxf(v.w,0.f));
}
__device__ __forceinline__ float sel4(const float4& v, int c) {
    return (c&3)==0 ? v.x : (c&3)==1 ? v.y : (c&3)==2 ? v.z : v.w;
}
__device__ __forceinline__ int sel4i(const int4& v, int c) {
    return (c&3)==0 ? v.x : (c&3)==1 ? v.y : (c&3)==2 ? v.z : v.w;
}
// Broadcast channel c (0..31) of this group's point: owner lane grp*8 + c/4.
// One SHFL serves all 4 groups at once.
__device__ __forceinline__ float bc(const float4& v, int c, int grp) {
    return __shfl_sync(0xffffffffu, sel4(v, c), (grp<<3) + (c>>2));
}

// K0: z0 = relu((x @ W2) * g2 + b2). 8 pts/warp: 4 groups x 2 sets, 8 lanes/pt.
__global__ void __launch_bounds__(KT_THREADS, 3)
k_transform(const float* __restrict__ x,
            const float* __restrict__ W2,
            const float* __restrict__ g2,
            const float* __restrict__ b2)
{
    __shared__ float4 sW2[DD*8];
    int tid = threadIdx.x;
    for (int i = tid; i < DD*8; i += KT_THREADS)
        sW2[i] = reinterpret_cast<const float4*>(W2)[i];
    __syncthreads();

    int lane = tid & 31, wid = tid >> 5;
    int grp = lane >> 3, sub = lane & 7;
    unsigned base = (blockIdx.x * 8 + wid) * 8;
    const float4* xf = reinterpret_cast<const float4*>(x);

    unsigned off[KT_SETS];
    float4 xv[KT_SETS], a[KT_SETS];
    #pragma unroll
    for (int s = 0; s < KT_SETS; s++) {
        off[s] = (base + s*4 + grp)*8 + sub;
        xv[s]  = __ldg(xf + off[s]);
        a[s]   = make_float4(0.f,0.f,0.f,0.f);
    }
    #pragma unroll
    for (int c = 0; c < DD; c++) {
        float4 w = sW2[c*8 + sub];
        #pragma unroll
        for (int s = 0; s < KT_SETS; s++)
            fma4(a[s], bc(xv[s], c, grp), w);
    }
    float4 gv = __ldg(reinterpret_cast<const float4*>(g2) + sub);
    float4 bv = __ldg(reinterpret_cast<const float4*>(b2) + sub);
    float4* za = reinterpret_cast<float4*>(g_za);
    #pragma unroll
    for (int s = 0; s < KT_SETS; s++)
        za[off[s]] = relu4(affine4(a[s], gv, bv));
}

// One network block fused with the NEXT block's per-point transform.
// MODE 0: first (init acc/prev). MODE 1: middle. MODE 2: last (write out).
template<int MODE>
__global__ void __launch_bounds__(KB_THREADS, 3)
k_block(int zflag,
        const int*   __restrict__ idx,
        const float* __restrict__ W1,  const float* __restrict__ g1,  const float* __restrict__ b1,
        const float* __restrict__ W2n, const float* __restrict__ g2n, const float* __restrict__ b2n,
        float* __restrict__ out)
{
    __shared__ float4 sW1[2*DD*8];            // 8 KB
    __shared__ float4 sW2[DD*8];              // 4 KB
    int tid = threadIdx.x;
    for (int i = tid; i < 2*DD*8; i += KB_THREADS)
        sW1[i] = reinterpret_cast<const float4*>(W1)[i];
    if (MODE != 2)
        for (int i = tid; i < DD*8; i += KB_THREADS)
            sW2[i] = reinterpret_cast<const float4*>(W2n)[i];
    __syncthreads();

    int lane = tid & 31, wid = tid >> 5;
    int grp = lane >> 3, sub = lane & 7;
    unsigned base = (blockIdx.x * KB_WARPS + wid) * PTS_PER_WARP;
    int b = base >> 16;                        // all 32 pts share the batch
    const float* z_in  = zflag ? g_zb : g_za;
    float*       z_out = zflag ? g_za : g_zb;
    const float4* zb = reinterpret_cast<const float4*>(z_in) + (unsigned)(b) * (NN*8u);

    // 512 neighbor indices for the warp's 32 points: four int4 per lane.
    // Point p = s*4+grp owns global int4 slots p*4+k/4; reg = s/2,
    // lane slot = (s&1)*16 + grp*4 + k/4.
    const int4* ip = reinterpret_cast<const int4*>(idx) + base*4u;
    int4 iv[4];
    #pragma unroll
    for (int r = 0; r < 4; r++)
        iv[r] = __ldg(ip + r*32 + lane);

    // Gather + max/mean over k. Per k per set: 1 SHFL + 1 LDG.128.
    // 128 independent LDG.128 per warp -> gather is throughput-bound, not
    // latency-bound.
    float4 mx[SETS], sm[SETS];
    #pragma unroll
    for (int s = 0; s < SETS; s++) {
        mx[s] = make_float4(-1e30f,-1e30f,-1e30f,-1e30f);
        sm[s] = make_float4(0.f,0.f,0.f,0.f);
    }
    #pragma unroll
    for (int k = 0; k < KK; k++) {
        #pragma unroll
        for (int s = 0; s < SETS; s++) {
            int slot = ((s & 1) << 4) + (grp << 2) + (k >> 2);
            int j = __shfl_sync(0xffffffffu, sel4i(iv[s >> 1], k), slot);
            float4 v = __ldg(zb + (unsigned)j*8u + sub);
            mx[s] = max4(mx[s], v);
            add4(sm[s], v);
        }
    }
    const float r16 = 1.f/KK;
    #pragma unroll
    for (int s = 0; s < SETS; s++) {
        sm[s].x *= r16; sm[s].y *= r16; sm[s].z *= r16; sm[s].w *= r16;
    }

    // Second 1x1 conv. Weight rows loaded from shared once per c, reused
    // across all 8 sets.
    float4 o[SETS];
    #pragma unroll
    for (int s = 0; s < SETS; s++) o[s] = make_float4(0.f,0.f,0.f,0.f);
    #pragma unroll
    for (int c = 0; c < DD; c++) {
        float4 wa = sW1[c*8 + sub];
        float4 wb = sW1[(DD + c)*8 + sub];
        #pragma unroll
        for (int s = 0; s < SETS; s++) {
            fma4(o[s], bc(mx[s], c, grp), wa);
            fma4(o[s], bc(sm[s], c, grp), wb);
        }
    }
    float4 g1v = __ldg(reinterpret_cast<const float4*>(g1) + sub);
    float4 b1v = __ldg(reinterpret_cast<const float4*>(b1) + sub);
    float4 xv[SETS];
    #pragma unroll
    for (int s = 0; s < SETS; s++)
        xv[s] = affine4(o[s], g1v, b1v);

    float4* accp  = reinterpret_cast<float4*>(g_acc);
    float4* prevp = reinterpret_cast<float4*>(g_prev);
    float4 sres[SETS];
    if (MODE == 0) {
        #pragma unroll
        for (int s = 0; s < SETS; s++) {
            unsigned off = (base + s*4 + grp)*8 + sub;
            accp[off]  = xv[s];
            prevp[off] = xv[s];
            sres[s] = xv[s];
        }
    } else if (MODE == 1) {
        #pragma unroll
        for (int s = 0; s < SETS; s++) {
            unsigned off = (base + s*4 + grp)*8 + sub;
            float4 p = prevp[off];
            sres[s] = make_float4(xv[s].x+p.x, xv[s].y+p.y, xv[s].z+p.z, xv[s].w+p.w);
            float4 ac = accp[off];
            add4(ac, xv[s]);
            accp[off]  = ac;
            prevp[off] = xv[s];
        }
    } else {
        float4* outp = reinterpret_cast<float4*>(out);
        #pragma unroll
        for (int s = 0; s < SETS; s++) {
            unsigned off = (base + s*4 + grp)*8 + sub;
            float4 ac = accp[off];
            add4(ac, xv[s]);
            outp[off] = lrelu4(ac);            // lrelu(x1+x2+x3+x4)
        }
        return;
    }

    // Fused next-block transform: z_next = relu((lrelu(s) @ W2n) * g2n + b2n)
    float4 t[SETS], a2[SETS];
    #pragma unroll
    for (int s = 0; s < SETS; s++) {
        t[s]  = lrelu4(sres[s]);
        a2[s] = make_float4(0.f,0.f,0.f,0.f);
    }
    #pragma unroll
    for (int c = 0; c < DD; c++) {
        float4 w = sW2[c*8 + sub];
        #pragma unroll
        for (int s = 0; s < SETS; s++)
            fma4(a2[s], bc(t[s], c, grp), w);
    }
    float4 g2v = __ldg(reinterpret_cast<const float4*>(g2n) + sub);
    float4 b2v = __ldg(reinterpret_cast<const float4*>(b2n) + sub);
    float4* zo = reinterpret_cast<float4*>(z_out);
    #pragma unroll
    for (int s = 0; s < SETS; s++) {
        unsigned off = (base + s*4 + grp)*8 + sub;
        zo[off] = relu4(affine4(a2[s], g2v, b2v));
    }
}

extern "C" void kernel_launch(void* const* d_in, const int* in_sizes, int n_in,
                              void* d_out, int out_size)
{
    const float* x   = (const float*)d_in[0];   // (2,65536,32)
    const int*   idx = (const int*)  d_in[1];   // (2,65536,16)
    const float* W2d = (const float*)d_in[2];   // (4,32,32)
    const float* g2  = (const float*)d_in[3];   // (4,32)
    const float* b2  = (const float*)d_in[4];   // (4,32)
    const float* W1d = (const float*)d_in[5];   // (4,64,32)
    const float* g1  = (const float*)d_in[6];   // (4,32)
    const float* b1  = (const float*)d_in[7];   // (4,32)
    float* out = (float*)d_out;

    // z0 from block-0 transform
    k_transform<<<KT_GRID, KT_THREADS>>>(x, W2d, g2, b2);

    dim3 blk(KB_THREADS), grd(KB_GRID);
    // block 0: reads g_za, writes x1 state + z1 into g_zb (tail = block-1 weights)
    k_block<0><<<grd, blk>>>(0, idx,
                             W1d + 0*2048, g1 + 0*32, b1 + 0*32,
                             W2d + 1*1024, g2 + 1*32, b2 + 1*32, out);
    // block 1: reads g_zb, writes z2 into g_za (tail = block-2 weights)
    k_block<1><<<grd, blk>>>(1, idx,
                             W1d + 1*2048, g1 + 1*32, b1 + 1*32,
                             W2d + 2*1024, g2 + 2*32, b2 + 2*32, out);
    // block 2: reads g_za, writes z3 into g_zb (tail = block-3 weights)
    k_block<1><<<grd, blk>>>(0, idx,
                             W1d + 2*2048, g1 + 2*32, b1 + 2*32,
                             W2d + 3*1024, g2 + 3*32, b2 + 3*32, out);
    // block 3: reads g_zb, writes final output
    k_block<2><<<grd, blk>>>(1, idx,
                             W1d + 3*2048, g1 + 3*32, b1 + 3*32,
                             W2d, g2, b2, out);
}

// round 11
// speedup vs baseline: 1.2988x; 1.2914x over previous
#include <cuda_runtime.h>

#define BB 2
#define NN 65536
#define KK 16
#define DD 32
#define NPTS (BB*NN)                 // 131072 points
#define WARPS_PER_BLOCK 8
#define THREADS (WARPS_PER_BLOCK*32)
#define SETS 4                       // temporal sets per warp
#define PTS_PER_WARP 16              // 4 spatial groups x 4 temporal sets
#define GRID (NPTS/(WARPS_PER_BLOCK*PTS_PER_WARP))   // 1024

// Scratch (no cudaMalloc allowed): ping-pong z buffers + residual state.
__device__ float g_za[NPTS*DD];
__device__ float g_zb[NPTS*DD];
__device__ float g_prev[NPTS*DD];
__device__ float g_acc [NPTS*DD];

__device__ __forceinline__ float lrelu1(float v) { return v >= 0.f ? v : 0.2f*v; }
__device__ __forceinline__ float4 lrelu4(float4 v) {
    return make_float4(lrelu1(v.x), lrelu1(v.y), lrelu1(v.z), lrelu1(v.w));
}
__device__ __forceinline__ float4 max4(float4 a, float4 b) {
    return make_float4(fmaxf(a.x,b.x), fmaxf(a.y,b.y), fmaxf(a.z,b.z), fmaxf(a.w,b.w));
}
__device__ __forceinline__ void add4(float4& a, float4 b) {
    a.x += b.x; a.y += b.y; a.z += b.z; a.w += b.w;
}
__device__ __forceinline__ void fma4(float4& o, float s, float4 w) {
    o.x = fmaf(s, w.x, o.x); o.y = fmaf(s, w.y, o.y);
    o.z = fmaf(s, w.z, o.z); o.w = fmaf(s, w.w, o.w);
}
__device__ __forceinline__ float4 affine4(float4 a, float4 g, float4 b) {
    return make_float4(fmaf(a.x,g.x,b.x), fmaf(a.y,g.y,b.y),
                       fmaf(a.z,g.z,b.z), fmaf(a.w,g.w,b.w));
}
__device__ __forceinline__ float4 relu4(float4 v) {
    return make_float4(fmaxf(v.x,0.f), fmaxf(v.y,0.f), fmaxf(v.z,0.f), fmaxf(v.w,0.f));
}
__device__ __forceinline__ float sel4(const float4& v, int c) {
    return (c&3)==0 ? v.x : (c&3)==1 ? v.y : (c&3)==2 ? v.z : v.w;
}
__device__ __forceinline__ int sel4i(const int4& v, int c) {
    return (c&3)==0 ? v.x : (c&3)==1 ? v.y : (c&3)==2 ? v.z : v.w;
}
// Broadcast channel c (0..31) of this group's point: owner lane grp*8 + c/4.
// One SHFL serves all 4 groups at once.
__device__ __forceinline__ float bc(const float4& v, int c, int grp) {
    return __shfl_sync(0xffffffffu, sel4(v, c), (grp<<3) + (c>>2));
}

// K0: z0 = relu((x @ W2) * g2 + b2). 16 pts/warp: 4 groups x 4 sets, 8 lanes/pt.
__global__ void __launch_bounds__(THREADS, 3)
k_transform(const float* __restrict__ x,
            const float* __restrict__ W2,
            const float* __restrict__ g2,
            const float* __restrict__ b2)
{
    __shared__ float4 sW2[DD*8];
    int tid = threadIdx.x;
    for (int i = tid; i < DD*8; i += THREADS)
        sW2[i] = reinterpret_cast<const float4*>(W2)[i];
    __syncthreads();

    int lane = tid & 31, wid = tid >> 5;
    int grp = lane >> 3, sub = lane & 7;
    unsigned base = (blockIdx.x * WARPS_PER_BLOCK + wid) * PTS_PER_WARP;
    const float4* xf = reinterpret_cast<const float4*>(x);

    float4 xv[SETS], a[SETS];
    #pragma unroll
    for (int s = 0; s < SETS; s++) {
        xv[s] = __ldg(xf + (base + s*4 + grp)*8u + sub);
        a[s]  = make_float4(0.f,0.f,0.f,0.f);
    }
    #pragma unroll
    for (int c = 0; c < DD; c++) {
        float4 w = sW2[c*8 + sub];
        #pragma unroll
        for (int s = 0; s < SETS; s++)
            fma4(a[s], bc(xv[s], c, grp), w);
    }
    float4 gv = __ldg(reinterpret_cast<const float4*>(g2) + sub);
    float4 bv = __ldg(reinterpret_cast<const float4*>(b2) + sub);
    float4* za = reinterpret_cast<float4*>(g_za);
    #pragma unroll
    for (int s = 0; s < SETS; s++)
        za[(base + s*4 + grp)*8u + sub] = relu4(affine4(a[s], gv, bv));
}

// One network block fused with the NEXT block's per-point transform.
// MODE 0: first (init acc/prev). MODE 1: middle. MODE 2: last (write out).
template<int MODE>
__global__ void __launch_bounds__(THREADS, 3)
k_block(int zflag,
        const int*   __restrict__ idx,
        const float* __restrict__ W1,  const float* __restrict__ g1,  const float* __restrict__ b1,
        const float* __restrict__ W2n, const float* __restrict__ g2n, const float* __restrict__ b2n,
        float* __restrict__ out)
{
    __shared__ float4 sW1[2*DD*8];            // 8 KB
    __shared__ float4 sW2[DD*8];              // 4 KB
    int tid = threadIdx.x;
    for (int i = tid; i < 2*DD*8; i += THREADS)
        sW1[i] = reinterpret_cast<const float4*>(W1)[i];
    if (MODE != 2)
        for (int i = tid; i < DD*8; i += THREADS)
            sW2[i] = reinterpret_cast<const float4*>(W2n)[i];
    __syncthreads();

    int lane = tid & 31, wid = tid >> 5;
    int grp = lane >> 3, sub = lane & 7;
    unsigned base = (blockIdx.x * WARPS_PER_BLOCK + wid) * PTS_PER_WARP;
    unsigned b = base >> 16;                   // all 16 pts share the batch
    const float* z_in  = zflag ? g_zb : g_za;
    float*       z_out = zflag ? g_za : g_zb;
    const float4* zb = reinterpret_cast<const float4*>(z_in) + b * (NN*8u);

    // 256 neighbor indices for the warp's 16 points: two int4 per lane.
    // iv0 = points base..base+7 (sets 0,1); iv1 = points base+8..15 (sets 2,3).
    const int4* ip = reinterpret_cast<const int4*>(idx) + base*4u;
    int4 iv0 = __ldg(ip + lane);
    int4 iv1 = __ldg(ip + 32 + lane);

    // Gather + max/mean over k. Per k per set: 1 SHFL + 1 LDG.128.
    // Each LDG.128 covers a point's FULL 128B row with 8 lanes (1 wf/line).
    float4 mx[SETS], sm[SETS];
    #pragma unroll
    for (int s = 0; s < SETS; s++) {
        mx[s] = make_float4(-1e30f,-1e30f,-1e30f,-1e30f);
        sm[s] = make_float4(0.f,0.f,0.f,0.f);
    }
    #pragma unroll
    for (int k = 0; k < KK; k++) {
        #pragma unroll
        for (int s = 0; s < SETS; s++) {
            int slot = ((s & 1) << 4) + (grp << 2) + (k >> 2);
            int j = __shfl_sync(0xffffffffu, sel4i((s & 2) ? iv1 : iv0, k), slot);
            float4 v = __ldg(zb + (unsigned)j*8u + sub);
            mx[s] = max4(mx[s], v);
            add4(sm[s], v);
        }
    }
    const float r16 = 1.f/KK;
    #pragma unroll
    for (int s = 0; s < SETS; s++) {
        sm[s].x *= r16; sm[s].y *= r16; sm[s].z *= r16; sm[s].w *= r16;
    }

    // Second 1x1 conv. Weight rows loaded from shared once per c, reused
    // across all 4 sets.
    float4 o[SETS];
    #pragma unroll
    for (int s = 0; s < SETS; s++) o[s] = make_float4(0.f,0.f,0.f,0.f);
    #pragma unroll
    for (int c = 0; c < DD; c++) {
        float4 wa = sW1[c*8 + sub];
        float4 wb = sW1[(DD + c)*8 + sub];
        #pragma unroll
        for (int s = 0; s < SETS; s++) {
            fma4(o[s], bc(mx[s], c, grp), wa);
            fma4(o[s], bc(sm[s], c, grp), wb);
        }
    }
    float4 g1v = __ldg(reinterpret_cast<const float4*>(g1) + sub);
    float4 b1v = __ldg(reinterpret_cast<const float4*>(b1) + sub);
    float4 xv[SETS];
    #pragma unroll
    for (int s = 0; s < SETS; s++)
        xv[s] = affine4(o[s], g1v, b1v);

    float4* accp  = reinterpret_cast<float4*>(g_acc);
    float4* prevp = reinterpret_cast<float4*>(g_prev);
    float4 sres[SETS];
    if (MODE == 0) {
        #pragma unroll
        for (int s = 0; s < SETS; s++) {
            unsigned off = (base + s*4 + grp)*8u + sub;
            accp[off]  = xv[s];
            prevp[off] = xv[s];
            sres[s] = xv[s];
        }
    } else if (MODE == 1) {
        #pragma unroll
        for (int s = 0; s < SETS; s++) {
            unsigned off = (base + s*4 + grp)*8u + sub;
            float4 p = prevp[off];
            sres[s] = make_float4(xv[s].x+p.x, xv[s].y+p.y, xv[s].z+p.z, xv[s].w+p.w);
            float4 ac = accp[off];
            add4(ac, xv[s]);
            accp[off]  = ac;
            prevp[off] = xv[s];
        }
    } else {
        float4* outp = reinterpret_cast<float4*>(out);
        #pragma unroll
        for (int s = 0; s < SETS; s++) {
            unsigned off = (base + s*4 + grp)*8u + sub;
            float4 ac = accp[off];
            add4(ac, xv[s]);
            outp[off] = lrelu4(ac);            // lrelu(x1+x2+x3+x4)
        }
        return;
    }

    // Fused next-block transform: z_next = relu((lrelu(s) @ W2n) * g2n + b2n)
    float4 t[SETS], a2[SETS];
    #pragma unroll
    for (int s = 0; s < SETS; s++) {
        t[s]  = lrelu4(sres[s]);
        a2[s] = make_float4(0.f,0.f,0.f,0.f);
    }
    #pragma unroll
    for (int c = 0; c < DD; c++) {
        float4 w = sW2[c*8 + sub];
        #pragma unroll
        for (int s = 0; s < SETS; s++)
            fma4(a2[s], bc(t[s], c, grp), w);
    }
    float4 g2v = __ldg(reinterpret_cast<const float4*>(g2n) + sub);
    float4 b2v = __ldg(reinterpret_cast<const float4*>(b2n) + sub);
    float4* zo = reinterpret_cast<float4*>(z_out);
    #pragma unroll
    for (int s = 0; s < SETS; s++)
        zo[(base + s*4 + grp)*8u + sub] = relu4(affine4(a2[s], g2v, b2v));
}

extern "C" void kernel_launch(void* const* d_in, const int* in_sizes, int n_in,
                              void* d_out, int out_size)
{
    const float* x   = (const float*)d_in[0];   // (2,65536,32)
    const int*   idx = (const int*)  d_in[1];   // (2,65536,16)
    const float* W2d = (const float*)d_in[2];   // (4,32,32)
    const float* g2  = (const float*)d_in[3];   // (4,32)
    const float* b2  = (const float*)d_in[4];   // (4,32)
    const float* W1d = (const float*)d_in[5];   // (4,64,32)
    const float* g1  = (const float*)d_in[6];   // (4,32)
    const float* b1  = (const float*)d_in[7];   // (4,32)
    float* out = (float*)d_out;

    dim3 blk(THREADS), grd(GRID);

    // z0 from block-0 transform
    k_transform<<<grd, blk>>>(x, W2d, g2, b2);

    // block 0: reads g_za, writes x1 state + z1 into g_zb (tail = block-1 weights)
    k_block<0><<<grd, blk>>>(0, idx,
                             W1d + 0*2048, g1 + 0*32, b1 + 0*32,
                             W2d + 1*1024, g2 + 1*32, b2 + 1*32, out);
    // block 1: reads g_zb, writes z2 into g_za (tail = block-2 weights)
    k_block<1><<<grd, blk>>>(1, idx,
                             W1d + 1*2048, g1 + 1*32, b1 + 1*32,
                             W2d + 2*1024, g2 + 2*32, b2 + 2*32, out);
    // block 2: reads g_za, writes z3 into g_zb (tail = block-3 weights)
    k_block<1><<<grd, blk>>>(0, idx,
                             W1d + 2*2048, g1 + 2*32, b1 + 2*32,
                             W2d + 3*1024, g2 + 3*32, b2 + 3*32, out);
    // block 3: reads g_zb, writes final output
    k_block<2><<<grd, blk>>>(1, idx,
                             W1d + 3*2048, g1 + 3*32, b1 + 3*32,
                             W2d, g2, b2, out);
}